// round 16
// baseline (speedup 1.0000x reference)
#include <cuda_runtime.h>
#include <cuda_bf16.h>
#include <cstdint>
#include <math.h>

#define BQ 1024
#define RSQRT2F 0.70710678118654752440f
#define EPSN 1e-6f

typedef __nv_bfloat16 bf;

// ===================== PTX helpers (sm_80+ baseline) =====================
__device__ __forceinline__ uint32_t smem_u32(const void* p) {
    uint32_t a;
    asm("{ .reg .u64 t; cvta.to.shared.u64 t, %1; cvt.u32.u64 %0, t; }" : "=r"(a) : "l"(p));
    return a;
}
#define CPASYNC16(d, s) asm volatile("cp.async.cg.shared.global [%0], [%1], 16;" :: "r"(d), "l"(s))
#define CPCOMMIT()      asm volatile("cp.async.commit_group;" ::: "memory")
#define CPWAIT2()       asm volatile("cp.async.wait_group 2;" ::: "memory")
#define CPWAIT1()       asm volatile("cp.async.wait_group 1;" ::: "memory")
#define CPWAIT0()       asm volatile("cp.async.wait_group 0;" ::: "memory")

#define LDSM4(r, addr) \
    asm volatile("ldmatrix.sync.aligned.m8n8.x4.shared.b16 {%0,%1,%2,%3}, [%4];" \
        : "=r"((r)[0]), "=r"((r)[1]), "=r"((r)[2]), "=r"((r)[3]) : "r"(addr))
#define LDSM2(r, addr) \
    asm volatile("ldmatrix.sync.aligned.m8n8.x2.shared.b16 {%0,%1}, [%2];" \
        : "=r"((r)[0]), "=r"((r)[1]) : "r"(addr))

#define MMA16816(d, a, b) \
    asm volatile("mma.sync.aligned.m16n8k16.row.col.f32.bf16.bf16.f32 " \
        "{%0,%1,%2,%3}, {%4,%5,%6,%7}, {%8,%9}, {%0,%1,%2,%3};" \
        : "+f"((d)[0]), "+f"((d)[1]), "+f"((d)[2]), "+f"((d)[3]) \
        : "r"((a)[0]), "r"((a)[1]), "r"((a)[2]), "r"((a)[3]), "r"((b)[0]), "r"((b)[1]))

// ===================== scratch (device globals) =====================
__device__ __align__(16) float g_xp  [8u  * 1024 * 256];
__device__ __align__(16) float g_xr  [8u  * 1024 * 512];
__device__ __align__(16) float g_h   [8u  * 1024 * 512];
__device__ __align__(16) float g_lin [8u  * 1024 * 512];
__device__ __align__(16) bf g_xph[8u * 1024 * 256],  g_xpl[8u * 1024 * 256];
__device__ __align__(16) bf g_hh [8u * 1024 * 512],  g_hl [8u * 1024 * 512];
__device__ __align__(16) bf g_lih[8u * 1024 * 512],  g_lil[8u * 1024 * 512];
__device__ __align__(16) bf g_Th [44u * 1024 * 512], g_Tl [44u * 1024 * 512];
__device__ __align__(16) bf g_lr1h[4u*256*256],  g_lr1l[4u*256*256];
__device__ __align__(16) bf g_ll1h[4u*512*256],  g_ll1l[4u*512*256];
__device__ __align__(16) bf g_w1h [20u*512*256], g_w1l [20u*512*256];
__device__ __align__(16) bf g_lrgh[4u*512*512],  g_lrgl[4u*512*512];
__device__ __align__(16) bf g_llgh[4u*512*512],  g_llgl[4u*512*512];
__device__ __align__(16) bf g_lr2h[4u*512*512],  g_lr2l[4u*512*512];
__device__ __align__(16) bf g_ll2h[4u*128*512],  g_ll2l[4u*128*512];
__device__ __align__(16) bf g_w2h [20u*128*512], g_w2l [20u*128*512];

__device__ __forceinline__ void bsplit(float v, bf& h, bf& l) {
    h = __float2bfloat16(v);
    l = __float2bfloat16(v - __bfloat162float(h));
}

// ===================== HMMA GEMM tile =====================
// C tile [BM x 128] at (brow, bcol): scale*(sum_s A_s[BM,K] @ W_s[128,K]^T + bias).
// bf16 hi/lo 3-term: AhBh + AhBl + AlBh, fp32 accum. NS-stage cp.async pipeline.
// smem rows: 64 bf16 (128 B), XOR-swizzled (chunk ^= row&7) -> conflict-free ldmatrix.
struct SegT { const bf *Ah, *Al, *Wh, *Wl; };

__device__ __forceinline__ uint32_t swz(int row, int c) {
    return (uint32_t)(row * 128 + (((c) ^ (row & 7)) << 4));
}

template<int BM, bool ILV, int NS>
__device__ __forceinline__ void tile_mma(const SegT* segs, int nseg, int K,
    float* C, int ldc, const float* bias, float scale, int brow, int bcol, int jbase)
{
    constexpr int A_B = BM * 128;            // bytes per A buffer (BM rows x 128B)
    constexpr int W_B = 128 * 128;
    constexpr int STAGE_B = 2 * A_B + 2 * W_B;
    constexpr int MT = BM / 32;

    extern __shared__ char smem_raw[];
    const uint32_t smb = smem_u32(smem_raw);
    const int tid  = threadIdx.x;
    const int lane = tid & 31;
    const int wid  = tid >> 5;
    const int warp_m = wid >> 2;
    const int warp_n = wid & 3;

    float acc[MT][4][4];
#pragma unroll
    for (int i = 0; i < MT; ++i)
#pragma unroll
        for (int j = 0; j < 4; ++j)
#pragma unroll
            for (int k = 0; k < 4; ++k) acc[i][j][k] = 0.f;

    const int kPerSeg = K >> 6;
    const int nch = nseg * kPerSeg;

    auto issue_loads = [&](int c) {
        const SegT sg = segs[c / kPerSeg];
        const int k0 = (c % kPerSeg) << 6;
        const uint32_t stb = smb + (uint32_t)(c % NS) * STAGE_B;
        const bf*      gp[4]   = {sg.Ah, sg.Al, sg.Wh, sg.Wl};
        const int      rows[4] = {BM, BM, 128, 128};
        const uint32_t boff[4] = {0, A_B, 2u * A_B, 2u * A_B + W_B};
#pragma unroll
        for (int b = 0; b < 4; ++b) {
            const int rbase = (b < 2) ? brow * BM : bcol * 128;
            const bf* g = gp[b] + (size_t)rbase * K + k0;
            for (int pos = tid; pos < rows[b] * 8; pos += 256) {
                const int row = pos >> 3, c8 = pos & 7;
                CPASYNC16(stb + boff[b] + swz(row, c8), g + (size_t)row * K + c8 * 8);
            }
        }
        CPCOMMIT();
    };

#pragma unroll
    for (int s = 0; s < NS - 1; ++s)
        if (s < nch) issue_loads(s);

    for (int c = 0; c < nch; ++c) {
        if (c + NS - 1 < nch) issue_loads(c + NS - 1);
        const int pend = (nch - 1 - c < NS - 1) ? (nch - 1 - c) : (NS - 1);
        if (pend >= 2)      CPWAIT2();
        else if (pend == 1) CPWAIT1();
        else                CPWAIT0();
        __syncthreads();

        const uint32_t stb = smb + (uint32_t)(c % NS) * STAGE_B;
        const uint32_t aH = stb;
        const uint32_t aL = stb + A_B;
        const uint32_t wH = stb + 2 * A_B;
        const uint32_t wL = stb + 2 * A_B + W_B;

        const int ar  = warp_m * (BM / 2) + (lane & 15);
        const int ahi = lane >> 4;                  // A chunk offset
        const int l16 = lane & 15;
        const int brn = warp_n * 32 + (l16 & 7);
        const int bhi = l16 >> 3;                   // B chunk offset

#pragma unroll
        for (int kk = 0; kk < 4; ++kk) {
            uint32_t ah[MT][4], al[MT][4], bh[4][2], bl[4][2];
#pragma unroll
            for (int mt = 0; mt < MT; ++mt) {
                const int row = ar + mt * 16;
                const uint32_t off = swz(row, kk * 2 + ahi);
                LDSM4(ah[mt], aH + off);
                LDSM4(al[mt], aL + off);
            }
#pragma unroll
            for (int nt = 0; nt < 4; ++nt) {
                const int row = brn + nt * 8;
                const uint32_t off = swz(row, kk * 2 + bhi);
                LDSM2(bh[nt], wH + off);
                LDSM2(bl[nt], wL + off);
            }
#pragma unroll
            for (int mt = 0; mt < MT; ++mt)
#pragma unroll
                for (int nt = 0; nt < 4; ++nt) {
                    MMA16816(acc[mt][nt], ah[mt], bh[nt]);
                    MMA16816(acc[mt][nt], ah[mt], bl[nt]);
                    MMA16816(acc[mt][nt], al[mt], bh[nt]);
                }
        }
        __syncthreads();
    }

    const int r0 = brow * BM + warp_m * (BM / 2) + (lane >> 2);
    const int c0 = bcol * 128 + warp_n * 32 + 2 * (lane & 3);
#pragma unroll
    for (int mt = 0; mt < MT; ++mt)
#pragma unroll
        for (int nt = 0; nt < 4; ++nt) {
            const int row = r0 + mt * 16;
            const int col = c0 + nt * 8;
            float b0 = 0.f, b1 = 0.f;
            if (bias) { b0 = __ldg(bias + col); b1 = __ldg(bias + col + 1); }
            float v00 = (acc[mt][nt][0] + b0) * scale;
            float v01 = (acc[mt][nt][1] + b1) * scale;
            float v10 = (acc[mt][nt][2] + b0) * scale;
            float v11 = (acc[mt][nt][3] + b1) * scale;
            if (!ILV) {
                *(float2*)(C + (size_t)row * ldc + col)       = make_float2(v00, v01);
                *(float2*)(C + (size_t)(row + 8) * ldc + col) = make_float2(v10, v11);
            } else {
                size_t o0 = ((size_t)(row & 1023) * 128 + col) * 8 + (jbase + (row >> 10));
                C[o0] = v00; C[o0 + 8] = v01;
                size_t o1 = ((size_t)((row + 8) & 1023) * 128 + col) * 8 + (jbase + ((row + 8) >> 10));
                C[o1] = v10; C[o1 + 8] = v11;
            }
        }
}

#define SMEM128_3 (3 * (2 * 128 * 128 + 2 * 128 * 128))   // 196608
#define SMEM64_2  (2 * (2 * 64  * 128 + 2 * 128 * 128))   // 98304

// blade-batched mv_linear (grid: x=col blk, y=row blk, z=blade)
struct Bat8T {
    const bf *Ah, *Al, *Wh, *Wl;
    float* C; const float* bias;
    int K, N; float scale;
};
__global__ void __launch_bounds__(256) gemm_bat8_t(Bat8T a) {
    const int gmap8[8] = {0,1,1,1,2,2,2,3};
    const int z = blockIdx.z;
    SegT s;
    const size_t ao = (size_t)z * BQ * a.K;
    const size_t wo = (size_t)gmap8[z] * a.N * a.K;
    s.Ah = a.Ah + ao; s.Al = a.Al + ao;
    s.Wh = a.Wh + wo; s.Wl = a.Wl + wo;
    tile_mma<128, false, 3>(&s, 1, a.K, a.C + (size_t)z * BQ * a.N, a.N,
             (z == 0) ? a.bias : nullptr, a.scale, blockIdx.y, blockIdx.x, 0);
}

// two mv_linears sharing A (lrg -> C1, llg -> C2 with bias); grid.z in [0,16)
struct Bat16T {
    const bf *Ah, *Al, *W1h, *W1l, *W2h, *W2l;
    float *C1, *C2; const float* bias2;
    int K, N;
};
__global__ void __launch_bounds__(256) gemm_bat16_t(Bat16T a) {
    const int gmap8[8] = {0,1,1,1,2,2,2,3};
    const int z = blockIdx.z;
    const int zz = z & 7;
    SegT s;
    const size_t ao = (size_t)zz * BQ * a.K;
    const size_t wo = (size_t)gmap8[zz] * a.N * a.K;
    s.Ah = a.Ah + ao; s.Al = a.Al + ao;
    if (z < 8) { s.Wh = a.W1h + wo; s.Wl = a.W1l + wo; }
    else       { s.Wh = a.W2h + wo; s.Wl = a.W2l + wo; }
    float* C = ((z < 8) ? a.C1 : a.C2) + (size_t)zz * BQ * a.N;
    tile_mma<128, false, 3>(&s, 1, a.K, C, a.N,
             (z == 8) ? a.bias2 : nullptr, 1.0f, blockIdx.y, blockIdx.x, 0);
}

// grade-fused segmented GEMM
struct GradeT { SegT segs[7]; int nseg; float* C; const float* bias; int jbase; };
struct FusedT { GradeT g[4]; int K; int N; float scale; };
template<int BM, bool ILV, int NS>
__global__ void __launch_bounds__(256) gemm_fused_t(FusedT f) {
    const int c0 = 1024 / BM;
    const int y = blockIdx.y;
    int g, brow;
    if      (y < c0)     { g = 0; brow = y; }
    else if (y < 4 * c0) { g = 1; brow = y - c0; }
    else if (y < 7 * c0) { g = 2; brow = y - 4 * c0; }
    else                 { g = 3; brow = y - 7 * c0; }
    tile_mma<BM, ILV, NS>(f.g[g].segs, f.g[g].nseg, f.K, f.g[g].C, f.N, f.g[g].bias,
                          f.scale, brow, blockIdx.x, f.g[g].jbase);
}

// ===================== elementwise kernels =====================
__device__ __forceinline__ float sigmoidf_(float v) { return 1.0f / (1.0f + expf(-v)); }

// single-launch planarize of all 8 weight tensors (job table in grid.y)
struct PlanJob { const float* src; bf* oh; bf* ol; int MN; int G; };
struct PlanArgs { PlanJob j[8]; };
__global__ void k_planarize_all(PlanArgs a) {
    const PlanJob jb = a.j[blockIdx.y];
    int idx = blockIdx.x * blockDim.x + threadIdx.x;
    if (idx >= jb.MN) return;
    const float* src = jb.src + (size_t)idx * jb.G;
    for (int g4 = 0; g4 < jb.G; g4 += 4) {
        float4 v = *(const float4*)(src + g4);
        float vv[4] = {v.x, v.y, v.z, v.w};
#pragma unroll
        for (int jj = 0; jj < 4; ++jj) {
            bf h, l; bsplit(vv[jj], h, l);
            size_t o = (size_t)(g4 + jj) * jb.MN + idx;
            jb.oh[o] = h; jb.ol[o] = l;
        }
    }
}

__global__ void k_transpose_bf(const float* __restrict__ x, float* __restrict__ xp,
                               bf* __restrict__ hi, bf* __restrict__ lo, int N) {
    int idx = blockIdx.x * blockDim.x + threadIdx.x;
    if (idx >= BQ * N) return;
    size_t plane = (size_t)BQ * N;
    const float* src = x + (size_t)idx * 8;
#pragma unroll
    for (int i = 0; i < 8; ++i) {
        float v = src[i];
        xp[plane * i + idx] = v;
        bf h, l; bsplit(v, h, l);
        hi[plane * i + idx] = h; lo[plane * i + idx] = l;
    }
}

__global__ void k_mvsilu_split(float* v, const float* __restrict__ a, const float* __restrict__ b,
                               bf* __restrict__ hi, bf* __restrict__ lo, int M) {
    int idx = blockIdx.x * blockDim.x + threadIdx.x;
    if (idx >= BQ * M) return;
    int m = idx % M;
    size_t plane = (size_t)BQ * M;
    float t[8];
#pragma unroll
    for (int i = 0; i < 8; ++i) t[i] = v[plane * i + idx];
    float inv[4];
    inv[0] = t[0];
    inv[1] = t[1]*t[1] + t[2]*t[2] + t[3]*t[3];
    inv[2] = t[4]*t[4] + t[5]*t[5] + t[6]*t[6];
    inv[3] = t[7]*t[7];
    float s[4];
#pragma unroll
    for (int g = 0; g < 4; ++g)
        s[g] = sigmoidf_(a[m * 4 + g] * inv[g] + b[m * 4 + g]);
    const int gm[8] = {0,1,1,1,2,2,2,3};
#pragma unroll
    for (int i = 0; i < 8; ++i) {
        float o = t[i] * s[gm[i]];
        v[plane * i + idx] = o;
        bf h, l; bsplit(o, h, l);
        hi[plane * i + idx] = h; lo[plane * i + idx] = l;
    }
}

// pair features with normalization of r folded in; emits 44 bf16 hi/lo planes
__global__ void k_pairfeat_norm(const float* __restrict__ xp, const float* __restrict__ rraw,
                                const float* __restrict__ na,
                                bf* __restrict__ Th, bf* __restrict__ Tl, int N) {
    int idx = blockIdx.x * blockDim.x + threadIdx.x;
    size_t plane = (size_t)BQ * N;
    if (idx >= (int)plane) return;
    int m = idx % N;
    float x[8], r[8];
#pragma unroll
    for (int i = 0; i < 8; ++i) { x[i] = xp[plane * i + idx]; r[i] = rraw[plane * i + idx]; }
    {
        float q[4];
        q[0] = r[0]*r[0];
        q[1] = r[1]*r[1] + r[2]*r[2] + r[3]*r[3];
        q[2] = r[4]*r[4] + r[5]*r[5] + r[6]*r[6];
        q[3] = r[7]*r[7];
        float inv[4];
#pragma unroll
        for (int g = 0; g < 4; ++g) {
            float sa = sigmoidf_(na[m * 4 + g]);
            inv[g] = 1.0f / (sa * (sqrtf(q[g]) - 1.0f) + 1.0f + EPSN);
        }
        const int gm[8] = {0,1,1,1,2,2,2,3};
#pragma unroll
        for (int i = 0; i < 8; ++i) r[i] *= inv[gm[i]];
    }
    float t[44];
    t[0]  = x[0]*r[0];
    t[1]  = x[1]*r[1] + x[2]*r[2] + x[3]*r[3];
    t[2]  = -(x[4]*r[4] + x[5]*r[5] + x[6]*r[6]);
    t[3]  = -x[7]*r[7];
    t[4]  = x[0]*r[1];  t[5]  = x[0]*r[2];  t[6]  = x[0]*r[3];
    t[7]  = x[1]*r[0];  t[8]  = x[2]*r[0];  t[9]  = x[3]*r[0];
    t[10] = -x[2]*r[4] - x[3]*r[5];
    t[11] =  x[1]*r[4] - x[3]*r[6];
    t[12] =  x[1]*r[5] + x[2]*r[6];
    t[13] =  x[4]*r[2] + x[5]*r[3];
    t[14] = -x[4]*r[1] + x[6]*r[3];
    t[15] = -x[5]*r[1] - x[6]*r[2];
    t[16] = -x[6]*r[7]; t[17] =  x[5]*r[7]; t[18] = -x[4]*r[7];
    t[19] = -x[7]*r[6]; t[20] =  x[7]*r[5]; t[21] = -x[7]*r[4];
    t[22] = x[0]*r[4];  t[23] = x[0]*r[5];  t[24] = x[0]*r[6];
    t[25] = x[1]*r[2] - x[2]*r[1];
    t[26] = x[1]*r[3] - x[3]*r[1];
    t[27] = x[2]*r[3] - x[3]*r[2];
    t[28] =  x[3]*r[7]; t[29] = -x[2]*r[7]; t[30] =  x[1]*r[7];
    t[31] = x[4]*r[0];  t[32] = x[5]*r[0];  t[33] = x[6]*r[0];
    t[34] = x[6]*r[5] - x[5]*r[6];
    t[35] = x[4]*r[6] - x[6]*r[4];
    t[36] = x[5]*r[4] - x[4]*r[5];
    t[37] =  x[7]*r[3]; t[38] = -x[7]*r[2]; t[39] =  x[7]*r[1];
    t[40] = x[0]*r[7];
    t[41] = x[1]*r[6] - x[2]*r[5] + x[3]*r[4];
    t[42] = x[4]*r[3] - x[5]*r[2] + x[6]*r[1];
    t[43] = x[7]*r[0];
#pragma unroll
    for (int i = 0; i < 44; ++i) {
        bf h, l; bsplit(t[i], h, l);
        Th[plane * i + idx] = h; Tl[plane * i + idx] = l;
    }
}

// channel-wise GP (with r normalization folded) + combine (/sqrt2) + MVSiLU
__global__ void k_cw_split(const float* __restrict__ hp, const float* __restrict__ rraw,
                           float* linp, const float* __restrict__ wg,
                           const float* __restrict__ nga,
                           const float* __restrict__ aa, const float* __restrict__ ab,
                           bf* __restrict__ hi, bf* __restrict__ lo) {
    const int M = 512;
    int idx = blockIdx.x * blockDim.x + threadIdx.x;
    size_t plane = (size_t)BQ * M;
    if (idx >= (int)plane) return;
    int n = idx % M;
    float x[8], r[8];
#pragma unroll
    for (int i = 0; i < 8; ++i) { x[i] = hp[plane * i + idx]; r[i] = rraw[plane * i + idx]; }
    {
        float q[4];
        q[0] = r[0]*r[0];
        q[1] = r[1]*r[1] + r[2]*r[2] + r[3]*r[3];
        q[2] = r[4]*r[4] + r[5]*r[5] + r[6]*r[6];
        q[3] = r[7]*r[7];
        float inv[4];
#pragma unroll
        for (int g = 0; g < 4; ++g) {
            float sa = sigmoidf_(nga[n * 4 + g]);
            inv[g] = 1.0f / (sa * (sqrtf(q[g]) - 1.0f) + 1.0f + EPSN);
        }
        const int gm[8] = {0,1,1,1,2,2,2,3};
#pragma unroll
        for (int i = 0; i < 8; ++i) r[i] *= inv[gm[i]];
    }
    float x0=x[0],x1=x[1],x2=x[2],x3=x[3],x4=x[4],x5=x[5],x6=x[6],x7=x[7];
    float r0=r[0],r1=r[1],r2=r[2],r3=r[3],r4=r[4],r5=r[5],r6=r[6],r7=r[7];
    const float* w = wg + n * 20;
    float o0 = w[0]*(x0*r0) + w[4]*(x1*r1 + x2*r2 + x3*r3)
             - w[10]*(x4*r4 + x5*r5 + x6*r6) - w[16]*(x7*r7);
    float o1 = w[1]*x0*r1 + w[5]*x1*r0 + w[6]*(-x2*r4 - x3*r5)
             + w[11]*( x4*r2 + x5*r3) + w[12]*(-x6*r7) + w[17]*(-x7*r6);
    float o2 = w[1]*x0*r2 + w[5]*x2*r0 + w[6]*( x1*r4 - x3*r6)
             + w[11]*(-x4*r1 + x6*r3) + w[12]*( x5*r7) + w[17]*( x7*r5);
    float o3 = w[1]*x0*r3 + w[5]*x3*r0 + w[6]*( x1*r5 + x2*r6)
             + w[11]*(-x5*r1 - x6*r2) + w[12]*(-x4*r7) + w[17]*(-x7*r4);
    float o4 = w[2]*x0*r4 + w[7]*(x1*r2 - x2*r1) + w[8]*( x3*r7)
             + w[13]*x4*r0 + w[14]*(x6*r5 - x5*r6) + w[18]*( x7*r3);
    float o5 = w[2]*x0*r5 + w[7]*(x1*r3 - x3*r1) + w[8]*(-x2*r7)
             + w[13]*x5*r0 + w[14]*(x4*r6 - x6*r4) + w[18]*(-x7*r2);
    float o6 = w[2]*x0*r6 + w[7]*(x2*r3 - x3*r2) + w[8]*( x1*r7)
             + w[13]*x6*r0 + w[14]*(x5*r4 - x4*r5) + w[18]*( x7*r1);
    float o7 = w[3]*x0*r7 + w[9]*(x1*r6 - x2*r5 + x3*r4)
             + w[15]*(x4*r3 - x5*r2 + x6*r1) + w[19]*x7*r0;
    float t[8];
    float oarr[8] = {o0,o1,o2,o3,o4,o5,o6,o7};
#pragma unroll
    for (int i = 0; i < 8; ++i) t[i] = (linp[plane * i + idx] + oarr[i]) * RSQRT2F;
    float inv[4];
    inv[0] = t[0];
    inv[1] = t[1]*t[1] + t[2]*t[2] + t[3]*t[3];
    inv[2] = t[4]*t[4] + t[5]*t[5] + t[6]*t[6];
    inv[3] = t[7]*t[7];
    float s[4];
#pragma unroll
    for (int g = 0; g < 4; ++g)
        s[g] = sigmoidf_(aa[n * 4 + g] * inv[g] + ab[n * 4 + g]);
    const int gm[8] = {0,1,1,1,2,2,2,3};
#pragma unroll
    for (int i = 0; i < 8; ++i) {
        float o = t[i] * s[gm[i]];
        linp[plane * i + idx] = o;
        bf h, l; bsplit(o, h, l);
        hi[plane * i + idx] = h; lo[plane * i + idx] = l;
    }
}

// ===================== host =====================
static void* symaddr(const void* s) { void* p = nullptr; cudaGetSymbolAddress(&p, s); return p; }

extern "C" void kernel_launch(void* const* d_in, const int* in_sizes, int n_in,
                              void* d_out, int out_size) {
    (void)in_sizes; (void)n_in; (void)out_size;
    const float* x     = (const float*)d_in[0];
    const float* lr1_w = (const float*)d_in[1];
    const float* n1_a  = (const float*)d_in[2];
    const float* ll1_w = (const float*)d_in[3];
    const float* ll1_b = (const float*)d_in[4];
    const float* w1    = (const float*)d_in[5];
    const float* act_a = (const float*)d_in[6];
    const float* act_b = (const float*)d_in[7];
    const float* lrg_w = (const float*)d_in[8];
    const float* ng_a  = (const float*)d_in[9];
    const float* llg_w = (const float*)d_in[10];
    const float* llg_b = (const float*)d_in[11];
    const float* wg    = (const float*)d_in[12];
    const float* lr2_w = (const float*)d_in[13];
    const float* n2_a  = (const float*)d_in[14];
    const float* ll2_w = (const float*)d_in[15];
    const float* ll2_b = (const float*)d_in[16];
    const float* w2    = (const float*)d_in[17];
    float* out = (float*)d_out;

    cudaFuncSetAttribute(gemm_bat8_t,  cudaFuncAttributeMaxDynamicSharedMemorySize, SMEM128_3);
    cudaFuncSetAttribute(gemm_bat16_t, cudaFuncAttributeMaxDynamicSharedMemorySize, SMEM128_3);
    cudaFuncSetAttribute(gemm_fused_t<128, false, 3>, cudaFuncAttributeMaxDynamicSharedMemorySize, SMEM128_3);
    cudaFuncSetAttribute(gemm_fused_t<64, true, 2>,   cudaFuncAttributeMaxDynamicSharedMemorySize, SMEM64_2);

    float* xp   = (float*)symaddr(g_xp);
    float* xr   = (float*)symaddr(g_xr);
    float* h    = (float*)symaddr(g_h);
    float* lin  = (float*)symaddr(g_lin);
    bf* xph = (bf*)symaddr(g_xph); bf* xpl = (bf*)symaddr(g_xpl);
    bf* hh  = (bf*)symaddr(g_hh);  bf* hl  = (bf*)symaddr(g_hl);
    bf* lih = (bf*)symaddr(g_lih); bf* lil = (bf*)symaddr(g_lil);
    bf* Th  = (bf*)symaddr(g_Th);  bf* Tl  = (bf*)symaddr(g_Tl);
    bf* lr1h = (bf*)symaddr(g_lr1h); bf* lr1l = (bf*)symaddr(g_lr1l);
    bf* ll1h = (bf*)symaddr(g_ll1h); bf* ll1l = (bf*)symaddr(g_ll1l);
    bf* w1h  = (bf*)symaddr(g_w1h);  bf* w1l  = (bf*)symaddr(g_w1l);
    bf* lrgh = (bf*)symaddr(g_lrgh); bf* lrgl = (bf*)symaddr(g_lrgl);
    bf* llgh = (bf*)symaddr(g_llgh); bf* llgl = (bf*)symaddr(g_llgl);
    bf* lr2h = (bf*)symaddr(g_lr2h); bf* lr2l = (bf*)symaddr(g_lr2l);
    bf* ll2h = (bf*)symaddr(g_ll2h); bf* ll2l = (bf*)symaddr(g_ll2l);
    bf* w2h  = (bf*)symaddr(g_w2h);  bf* w2l  = (bf*)symaddr(g_w2l);

    const int TPB = 256;
    auto nb = [](int total) { return (total + 255) / 256; };

    // single-launch planarize of all weights
    {
        PlanArgs pa;
        pa.j[0] = {lr1_w, lr1h, lr1l, 256*256, 4};
        pa.j[1] = {ll1_w, ll1h, ll1l, 512*256, 4};
        pa.j[2] = {w1,    w1h,  w1l,  512*256, 20};
        pa.j[3] = {lrg_w, lrgh, lrgl, 512*512, 4};
        pa.j[4] = {llg_w, llgh, llgl, 512*512, 4};
        pa.j[5] = {lr2_w, lr2h, lr2l, 512*512, 4};
        pa.j[6] = {ll2_w, ll2h, ll2l, 128*512, 4};
        pa.j[7] = {w2,    w2h,  w2l,  128*512, 20};
        k_planarize_all<<<dim3(1024, 8), TPB>>>(pa);
    }

    // planarize x (fp32 + hi/lo)
    k_transpose_bf<<<nb(BQ*256), TPB>>>(x, xp, xph, xpl, 256);

    static const int j0g[4]   = {0, 1, 4, 7};
    static const int sg[4]    = {1, 3, 3, 1};
    static const int tbase[4] = {0, 4, 22, 40};
    static const int ntri[4]  = {4, 6, 6, 4};
    static const int tri0[6] = {0, 4, 10, 16, 0, 0};
    static const int tri1[6] = {1, 5, 6, 11, 12, 17};
    static const int tri2[6] = {2, 7, 8, 13, 14, 18};
    static const int tri3[6] = {3, 9, 15, 19, 0, 0};
    const int* tris[4] = {tri0, tri1, tri2, tri3};

    // ===== stage 1: xr_raw = mv_linear(x, lr1_w); norm folded into pairfeat =====
    {
        Bat8T a;
        a.Ah = xph; a.Al = xpl; a.Wh = lr1h; a.Wl = lr1l;
        a.C = xr; a.bias = nullptr; a.K = 256; a.N = 256; a.scale = 1.0f;
        gemm_bat8_t<<<dim3(2, 8, 8), 256, SMEM128_3>>>(a);
    }
    k_pairfeat_norm<<<nb(BQ*256), TPB>>>(xp, xr, n1_a, Th, Tl, 256);

    // fused layer 1: h = (mv_linear(x,ll1)+b + fcgp(x,xr,w1)) / sqrt2
    {
        FusedT f; f.K = 256; f.N = 512; f.scale = RSQRT2F;
        size_t plane = (size_t)BQ * 256;
        for (int g = 0; g < 4; ++g) {
            GradeT& gg = f.g[g];
            gg.nseg = 1 + ntri[g];
            gg.C = h + (size_t)j0g[g] * BQ * 512;
            gg.bias = (g == 0) ? ll1_b : nullptr;
            gg.jbase = j0g[g];
            gg.segs[0].Ah = xph + (size_t)j0g[g] * plane;
            gg.segs[0].Al = xpl + (size_t)j0g[g] * plane;
            gg.segs[0].Wh = ll1h + (size_t)g * 512 * 256;
            gg.segs[0].Wl = ll1l + (size_t)g * 512 * 256;
            for (int c = 0; c < ntri[g]; ++c) {
                size_t to = (size_t)(tbase[g] + c * sg[g]) * plane;
                size_t wo = (size_t)tris[g][c] * 512 * 256;
                gg.segs[c + 1].Ah = Th + to; gg.segs[c + 1].Al = Tl + to;
                gg.segs[c + 1].Wh = w1h + wo; gg.segs[c + 1].Wl = w1l + wo;
            }
            for (int c = ntri[g] + 1; c < 7; ++c) gg.segs[c] = gg.segs[0];
        }
        gemm_fused_t<128, false, 3><<<dim3(4, 64), 256, SMEM128_3>>>(f);
    }
    k_mvsilu_split<<<nb(BQ*512), TPB>>>(h, act_a, act_b, hh, hl, 512);

    // ===== stage 2: lrg + llg merged; cw_split normalizes lrg output inline =====
    {
        Bat16T a;
        a.Ah = hh; a.Al = hl;
        a.W1h = lrgh; a.W1l = lrgl; a.W2h = llgh; a.W2l = llgl;
        a.C1 = xr; a.C2 = lin; a.bias2 = llg_b;
        a.K = 512; a.N = 512;
        gemm_bat16_t<<<dim3(4, 8, 16), 256, SMEM128_3>>>(a);
    }
    k_cw_split<<<nb(BQ*512), TPB>>>(h, xr, lin, wg, ng_a, act_a, act_b, lih, lil);
    // h_new lives in `lin` (fp32) and lih/lil (bf16)

    // ===== stage 3: fcgp2 -> out (interleaved epilogue) =====
    {
        Bat8T a;
        a.Ah = lih; a.Al = lil; a.Wh = lr2h; a.Wl = lr2l;
        a.C = xr; a.bias = nullptr; a.K = 512; a.N = 512; a.scale = 1.0f;
        gemm_bat8_t<<<dim3(4, 8, 8), 256, SMEM128_3>>>(a);
    }
    k_pairfeat_norm<<<nb(BQ*512), TPB>>>(lin, xr, n2_a, Th, Tl, 512);
    {
        FusedT f; f.K = 512; f.N = 128; f.scale = RSQRT2F;
        size_t plane = (size_t)BQ * 512;
        for (int g = 0; g < 4; ++g) {
            GradeT& gg = f.g[g];
            gg.nseg = 1 + ntri[g];
            gg.C = out;                      // interleaved direct write
            gg.bias = (g == 0) ? ll2_b : nullptr;
            gg.jbase = j0g[g];
            gg.segs[0].Ah = lih + (size_t)j0g[g] * plane;
            gg.segs[0].Al = lil + (size_t)j0g[g] * plane;
            gg.segs[0].Wh = ll2h + (size_t)g * 128 * 512;
            gg.segs[0].Wl = ll2l + (size_t)g * 128 * 512;
            for (int c = 0; c < ntri[g]; ++c) {
                size_t to = (size_t)(tbase[g] + c * sg[g]) * plane;
                size_t wo = (size_t)tris[g][c] * 128 * 512;
                gg.segs[c + 1].Ah = Th + to; gg.segs[c + 1].Al = Tl + to;
                gg.segs[c + 1].Wh = w2h + wo; gg.segs[c + 1].Wl = w2l + wo;
            }
            for (int c = ntri[g] + 1; c < 7; ++c) gg.segs[c] = gg.segs[0];
        }
        gemm_fused_t<64, true, 2><<<dim3(1, 128), 256, SMEM64_2>>>(f);
    }
}

// round 17
// speedup vs baseline: 1.0026x; 1.0026x over previous
#include <cuda_runtime.h>
#include <cuda_bf16.h>
#include <cstdint>
#include <math.h>

#define BQ 1024
#define RSQRT2F 0.70710678118654752440f
#define EPSN 1e-6f

typedef __nv_bfloat16 bf;

// ===================== PTX helpers (sm_80+ baseline) =====================
__device__ __forceinline__ uint32_t smem_u32(const void* p) {
    uint32_t a;
    asm("{ .reg .u64 t; cvta.to.shared.u64 t, %1; cvt.u32.u64 %0, t; }" : "=r"(a) : "l"(p));
    return a;
}
#define CPASYNC16(d, s) asm volatile("cp.async.cg.shared.global [%0], [%1], 16;" :: "r"(d), "l"(s))
#define CPCOMMIT()      asm volatile("cp.async.commit_group;" ::: "memory")
#define CPWAIT2()       asm volatile("cp.async.wait_group 2;" ::: "memory")
#define CPWAIT1()       asm volatile("cp.async.wait_group 1;" ::: "memory")
#define CPWAIT0()       asm volatile("cp.async.wait_group 0;" ::: "memory")

#define LDSM4(r, addr) \
    asm volatile("ldmatrix.sync.aligned.m8n8.x4.shared.b16 {%0,%1,%2,%3}, [%4];" \
        : "=r"((r)[0]), "=r"((r)[1]), "=r"((r)[2]), "=r"((r)[3]) : "r"(addr))
#define LDSM2(r, addr) \
    asm volatile("ldmatrix.sync.aligned.m8n8.x2.shared.b16 {%0,%1}, [%2];" \
        : "=r"((r)[0]), "=r"((r)[1]) : "r"(addr))

#define MMA16816(d, a, b) \
    asm volatile("mma.sync.aligned.m16n8k16.row.col.f32.bf16.bf16.f32 " \
        "{%0,%1,%2,%3}, {%4,%5,%6,%7}, {%8,%9}, {%0,%1,%2,%3};" \
        : "+f"((d)[0]), "+f"((d)[1]), "+f"((d)[2]), "+f"((d)[3]) \
        : "r"((a)[0]), "r"((a)[1]), "r"((a)[2]), "r"((a)[3]), "r"((b)[0]), "r"((b)[1]))

// ===================== scratch (device globals) =====================
__device__ __align__(16) float g_xp  [8u  * 1024 * 256];
__device__ __align__(16) float g_xr  [8u  * 1024 * 512];
__device__ __align__(16) float g_h   [8u  * 1024 * 512];
__device__ __align__(16) float g_lin [8u  * 1024 * 512];
__device__ __align__(16) bf g_xph[8u * 1024 * 256],  g_xpl[8u * 1024 * 256];
__device__ __align__(16) bf g_hh [8u * 1024 * 512],  g_hl [8u * 1024 * 512];
__device__ __align__(16) bf g_lih[8u * 1024 * 512],  g_lil[8u * 1024 * 512];
__device__ __align__(16) bf g_Th [44u * 1024 * 512], g_Tl [44u * 1024 * 512];
__device__ __align__(16) bf g_lr1h[4u*256*256],  g_lr1l[4u*256*256];
__device__ __align__(16) bf g_ll1h[4u*512*256],  g_ll1l[4u*512*256];
__device__ __align__(16) bf g_w1h [20u*512*256], g_w1l [20u*512*256];
__device__ __align__(16) bf g_lrgh[4u*512*512],  g_lrgl[4u*512*512];
__device__ __align__(16) bf g_llgh[4u*512*512],  g_llgl[4u*512*512];
__device__ __align__(16) bf g_lr2h[4u*512*512],  g_lr2l[4u*512*512];
__device__ __align__(16) bf g_ll2h[4u*128*512],  g_ll2l[4u*128*512];
__device__ __align__(16) bf g_w2h [20u*128*512], g_w2l [20u*128*512];

__device__ __forceinline__ void bsplit(float v, bf& h, bf& l) {
    h = __float2bfloat16(v);
    l = __float2bfloat16(v - __bfloat162float(h));
}

// ===================== HMMA GEMM tile =====================
// C tile [BM x 128] at (brow, bcol): scale*(sum_s A_s[BM,K] @ W_s[128,K]^T + bias).
// bf16 hi/lo 3-term: AhBh + AhBl + AlBh, fp32 accum. NS-stage cp.async pipeline.
// smem rows: 64 bf16 (128 B), XOR-swizzled (chunk ^= row&7) -> conflict-free ldmatrix.
struct SegT { const bf *Ah, *Al, *Wh, *Wl; };

__device__ __forceinline__ uint32_t swz(int row, int c) {
    return (uint32_t)(row * 128 + (((c) ^ (row & 7)) << 4));
}

template<int BM, bool ILV, int NS>
__device__ __forceinline__ void tile_mma(const SegT* segs, int nseg, int K,
    float* C, int ldc, const float* bias, float scale, int brow, int bcol, int jbase)
{
    constexpr int A_B = BM * 128;            // bytes per A buffer (BM rows x 128B)
    constexpr int W_B = 128 * 128;
    constexpr int STAGE_B = 2 * A_B + 2 * W_B;
    constexpr int MT = BM / 32;

    extern __shared__ char smem_raw[];
    const uint32_t smb = smem_u32(smem_raw);
    const int tid  = threadIdx.x;
    const int lane = tid & 31;
    const int wid  = tid >> 5;
    const int warp_m = wid >> 2;
    const int warp_n = wid & 3;

    float acc[MT][4][4];
#pragma unroll
    for (int i = 0; i < MT; ++i)
#pragma unroll
        for (int j = 0; j < 4; ++j)
#pragma unroll
            for (int k = 0; k < 4; ++k) acc[i][j][k] = 0.f;

    const int kPerSeg = K >> 6;
    const int nch = nseg * kPerSeg;

    auto issue_loads = [&](int c) {
        const SegT sg = segs[c / kPerSeg];
        const int k0 = (c % kPerSeg) << 6;
        const uint32_t stb = smb + (uint32_t)(c % NS) * STAGE_B;
        const bf*      gp[4]   = {sg.Ah, sg.Al, sg.Wh, sg.Wl};
        const int      rows[4] = {BM, BM, 128, 128};
        const uint32_t boff[4] = {0, A_B, 2u * A_B, 2u * A_B + W_B};
#pragma unroll
        for (int b = 0; b < 4; ++b) {
            const int rbase = (b < 2) ? brow * BM : bcol * 128;
            const bf* g = gp[b] + (size_t)rbase * K + k0;
            for (int pos = tid; pos < rows[b] * 8; pos += 256) {
                const int row = pos >> 3, c8 = pos & 7;
                CPASYNC16(stb + boff[b] + swz(row, c8), g + (size_t)row * K + c8 * 8);
            }
        }
        CPCOMMIT();
    };

#pragma unroll
    for (int s = 0; s < NS - 1; ++s)
        if (s < nch) issue_loads(s);

    for (int c = 0; c < nch; ++c) {
        if (c + NS - 1 < nch) issue_loads(c + NS - 1);
        const int pend = (nch - 1 - c < NS - 1) ? (nch - 1 - c) : (NS - 1);
        if (pend >= 2)      CPWAIT2();
        else if (pend == 1) CPWAIT1();
        else                CPWAIT0();
        __syncthreads();

        const uint32_t stb = smb + (uint32_t)(c % NS) * STAGE_B;
        const uint32_t aH = stb;
        const uint32_t aL = stb + A_B;
        const uint32_t wH = stb + 2 * A_B;
        const uint32_t wL = stb + 2 * A_B + W_B;

        const int ar  = warp_m * (BM / 2) + (lane & 15);
        const int ahi = lane >> 4;                  // A chunk offset
        const int l16 = lane & 15;
        const int brn = warp_n * 32 + (l16 & 7);
        const int bhi = l16 >> 3;                   // B chunk offset

#pragma unroll
        for (int kk = 0; kk < 4; ++kk) {
            uint32_t ah[MT][4], al[MT][4], bh[4][2], bl[4][2];
#pragma unroll
            for (int mt = 0; mt < MT; ++mt) {
                const int row = ar + mt * 16;
                const uint32_t off = swz(row, kk * 2 + ahi);
                LDSM4(ah[mt], aH + off);
                LDSM4(al[mt], aL + off);
            }
#pragma unroll
            for (int nt = 0; nt < 4; ++nt) {
                const int row = brn + nt * 8;
                const uint32_t off = swz(row, kk * 2 + bhi);
                LDSM2(bh[nt], wH + off);
                LDSM2(bl[nt], wL + off);
            }
#pragma unroll
            for (int mt = 0; mt < MT; ++mt)
#pragma unroll
                for (int nt = 0; nt < 4; ++nt) {
                    MMA16816(acc[mt][nt], ah[mt], bh[nt]);
                    MMA16816(acc[mt][nt], ah[mt], bl[nt]);
                    MMA16816(acc[mt][nt], al[mt], bh[nt]);
                }
        }
        __syncthreads();
    }

    const int r0 = brow * BM + warp_m * (BM / 2) + (lane >> 2);
    const int c0 = bcol * 128 + warp_n * 32 + 2 * (lane & 3);
#pragma unroll
    for (int mt = 0; mt < MT; ++mt)
#pragma unroll
        for (int nt = 0; nt < 4; ++nt) {
            const int row = r0 + mt * 16;
            const int col = c0 + nt * 8;
            float b0 = 0.f, b1 = 0.f;
            if (bias) { b0 = __ldg(bias + col); b1 = __ldg(bias + col + 1); }
            float v00 = (acc[mt][nt][0] + b0) * scale;
            float v01 = (acc[mt][nt][1] + b1) * scale;
            float v10 = (acc[mt][nt][2] + b0) * scale;
            float v11 = (acc[mt][nt][3] + b1) * scale;
            if (!ILV) {
                *(float2*)(C + (size_t)row * ldc + col)       = make_float2(v00, v01);
                *(float2*)(C + (size_t)(row + 8) * ldc + col) = make_float2(v10, v11);
            } else {
                size_t o0 = ((size_t)(row & 1023) * 128 + col) * 8 + (jbase + (row >> 10));
                C[o0] = v00; C[o0 + 8] = v01;
                size_t o1 = ((size_t)((row + 8) & 1023) * 128 + col) * 8 + (jbase + ((row + 8) >> 10));
                C[o1] = v10; C[o1 + 8] = v11;
            }
        }
}

#define SMEM128_3 (3 * (2 * 128 * 128 + 2 * 128 * 128))   // 196608
#define SMEM64_2  (2 * (2 * 64  * 128 + 2 * 128 * 128))   // 98304

// blade-batched mv_linear (grid: x=col blk, y=row blk, z=blade)
struct Bat8T {
    const bf *Ah, *Al, *Wh, *Wl;
    float* C; const float* bias;
    int K, N; float scale;
};
__global__ void __launch_bounds__(256) gemm_bat8_t(Bat8T a) {
    const int gmap8[8] = {0,1,1,1,2,2,2,3};
    const int z = blockIdx.z;
    SegT s;
    const size_t ao = (size_t)z * BQ * a.K;
    const size_t wo = (size_t)gmap8[z] * a.N * a.K;
    s.Ah = a.Ah + ao; s.Al = a.Al + ao;
    s.Wh = a.Wh + wo; s.Wl = a.Wl + wo;
    tile_mma<128, false, 3>(&s, 1, a.K, a.C + (size_t)z * BQ * a.N, a.N,
             (z == 0) ? a.bias : nullptr, a.scale, blockIdx.y, blockIdx.x, 0);
}

// two mv_linears sharing A (lrg -> C1, llg -> C2 with bias); grid.z in [0,16)
struct Bat16T {
    const bf *Ah, *Al, *W1h, *W1l, *W2h, *W2l;
    float *C1, *C2; const float* bias2;
    int K, N;
};
__global__ void __launch_bounds__(256) gemm_bat16_t(Bat16T a) {
    const int gmap8[8] = {0,1,1,1,2,2,2,3};
    const int z = blockIdx.z;
    const int zz = z & 7;
    SegT s;
    const size_t ao = (size_t)zz * BQ * a.K;
    const size_t wo = (size_t)gmap8[zz] * a.N * a.K;
    s.Ah = a.Ah + ao; s.Al = a.Al + ao;
    if (z < 8) { s.Wh = a.W1h + wo; s.Wl = a.W1l + wo; }
    else       { s.Wh = a.W2h + wo; s.Wl = a.W2l + wo; }
    float* C = ((z < 8) ? a.C1 : a.C2) + (size_t)zz * BQ * a.N;
    tile_mma<128, false, 3>(&s, 1, a.K, C, a.N,
             (z == 8) ? a.bias2 : nullptr, 1.0f, blockIdx.y, blockIdx.x, 0);
}

// grade-fused segmented GEMM
struct GradeT { SegT segs[7]; int nseg; float* C; const float* bias; int jbase; };
struct FusedT { GradeT g[4]; int K; int N; float scale; };
template<int BM, bool ILV, int NS>
__global__ void __launch_bounds__(256) gemm_fused_t(FusedT f) {
    const int c0 = 1024 / BM;
    const int y = blockIdx.y;
    int g, brow;
    if      (y < c0)     { g = 0; brow = y; }
    else if (y < 4 * c0) { g = 1; brow = y - c0; }
    else if (y < 7 * c0) { g = 2; brow = y - 4 * c0; }
    else                 { g = 3; brow = y - 7 * c0; }
    tile_mma<BM, ILV, NS>(f.g[g].segs, f.g[g].nseg, f.K, f.g[g].C, f.N, f.g[g].bias,
                          f.scale, brow, blockIdx.x, f.g[g].jbase);
}

// ===================== elementwise kernels =====================
__device__ __forceinline__ float sigmoidf_(float v) { return 1.0f / (1.0f + expf(-v)); }

// single-launch planarize of all 8 weight tensors (job table in grid.y)
struct PlanJob { const float* src; bf* oh; bf* ol; int MN; int G; };
struct PlanArgs { PlanJob j[8]; };
__global__ void k_planarize_all(PlanArgs a) {
    const PlanJob jb = a.j[blockIdx.y];
    int idx = blockIdx.x * blockDim.x + threadIdx.x;
    if (idx >= jb.MN) return;
    const float* src = jb.src + (size_t)idx * jb.G;
    for (int g4 = 0; g4 < jb.G; g4 += 4) {
        float4 v = *(const float4*)(src + g4);
        float vv[4] = {v.x, v.y, v.z, v.w};
#pragma unroll
        for (int jj = 0; jj < 4; ++jj) {
            bf h, l; bsplit(vv[jj], h, l);
            size_t o = (size_t)(g4 + jj) * jb.MN + idx;
            jb.oh[o] = h; jb.ol[o] = l;
        }
    }
}

__global__ void k_transpose_bf(const float* __restrict__ x, float* __restrict__ xp,
                               bf* __restrict__ hi, bf* __restrict__ lo, int N) {
    int idx = blockIdx.x * blockDim.x + threadIdx.x;
    if (idx >= BQ * N) return;
    size_t plane = (size_t)BQ * N;
    const float* src = x + (size_t)idx * 8;
#pragma unroll
    for (int i = 0; i < 8; ++i) {
        float v = src[i];
        xp[plane * i + idx] = v;
        bf h, l; bsplit(v, h, l);
        hi[plane * i + idx] = h; lo[plane * i + idx] = l;
    }
}

__global__ void k_mvsilu_split(float* v, const float* __restrict__ a, const float* __restrict__ b,
                               bf* __restrict__ hi, bf* __restrict__ lo, int M) {
    int idx = blockIdx.x * blockDim.x + threadIdx.x;
    if (idx >= BQ * M) return;
    int m = idx % M;
    size_t plane = (size_t)BQ * M;
    float t[8];
#pragma unroll
    for (int i = 0; i < 8; ++i) t[i] = v[plane * i + idx];
    float inv[4];
    inv[0] = t[0];
    inv[1] = t[1]*t[1] + t[2]*t[2] + t[3]*t[3];
    inv[2] = t[4]*t[4] + t[5]*t[5] + t[6]*t[6];
    inv[3] = t[7]*t[7];
    float s[4];
#pragma unroll
    for (int g = 0; g < 4; ++g)
        s[g] = sigmoidf_(a[m * 4 + g] * inv[g] + b[m * 4 + g]);
    const int gm[8] = {0,1,1,1,2,2,2,3};
#pragma unroll
    for (int i = 0; i < 8; ++i) {
        float o = t[i] * s[gm[i]];
        v[plane * i + idx] = o;
        bf h, l; bsplit(o, h, l);
        hi[plane * i + idx] = h; lo[plane * i + idx] = l;
    }
}

// pair features with normalization of r folded in; emits 44 bf16 hi/lo planes
__global__ void k_pairfeat_norm(const float* __restrict__ xp, const float* __restrict__ rraw,
                                const float* __restrict__ na,
                                bf* __restrict__ Th, bf* __restrict__ Tl, int N) {
    int idx = blockIdx.x * blockDim.x + threadIdx.x;
    size_t plane = (size_t)BQ * N;
    if (idx >= (int)plane) return;
    int m = idx % N;
    float x[8], r[8];
#pragma unroll
    for (int i = 0; i < 8; ++i) { x[i] = xp[plane * i + idx]; r[i] = rraw[plane * i + idx]; }
    {
        float q[4];
        q[0] = r[0]*r[0];
        q[1] = r[1]*r[1] + r[2]*r[2] + r[3]*r[3];
        q[2] = r[4]*r[4] + r[5]*r[5] + r[6]*r[6];
        q[3] = r[7]*r[7];
        float inv[4];
#pragma unroll
        for (int g = 0; g < 4; ++g) {
            float sa = sigmoidf_(na[m * 4 + g]);
            inv[g] = 1.0f / (sa * (sqrtf(q[g]) - 1.0f) + 1.0f + EPSN);
        }
        const int gm[8] = {0,1,1,1,2,2,2,3};
#pragma unroll
        for (int i = 0; i < 8; ++i) r[i] *= inv[gm[i]];
    }
    float t[44];
    t[0]  = x[0]*r[0];
    t[1]  = x[1]*r[1] + x[2]*r[2] + x[3]*r[3];
    t[2]  = -(x[4]*r[4] + x[5]*r[5] + x[6]*r[6]);
    t[3]  = -x[7]*r[7];
    t[4]  = x[0]*r[1];  t[5]  = x[0]*r[2];  t[6]  = x[0]*r[3];
    t[7]  = x[1]*r[0];  t[8]  = x[2]*r[0];  t[9]  = x[3]*r[0];
    t[10] = -x[2]*r[4] - x[3]*r[5];
    t[11] =  x[1]*r[4] - x[3]*r[6];
    t[12] =  x[1]*r[5] + x[2]*r[6];
    t[13] =  x[4]*r[2] + x[5]*r[3];
    t[14] = -x[4]*r[1] + x[6]*r[3];
    t[15] = -x[5]*r[1] - x[6]*r[2];
    t[16] = -x[6]*r[7]; t[17] =  x[5]*r[7]; t[18] = -x[4]*r[7];
    t[19] = -x[7]*r[6]; t[20] =  x[7]*r[5]; t[21] = -x[7]*r[4];
    t[22] = x[0]*r[4];  t[23] = x[0]*r[5];  t[24] = x[0]*r[6];
    t[25] = x[1]*r[2] - x[2]*r[1];
    t[26] = x[1]*r[3] - x[3]*r[1];
    t[27] = x[2]*r[3] - x[3]*r[2];
    t[28] =  x[3]*r[7]; t[29] = -x[2]*r[7]; t[30] =  x[1]*r[7];
    t[31] = x[4]*r[0];  t[32] = x[5]*r[0];  t[33] = x[6]*r[0];
    t[34] = x[6]*r[5] - x[5]*r[6];
    t[35] = x[4]*r[6] - x[6]*r[4];
    t[36] = x[5]*r[4] - x[4]*r[5];
    t[37] =  x[7]*r[3]; t[38] = -x[7]*r[2]; t[39] =  x[7]*r[1];
    t[40] = x[0]*r[7];
    t[41] = x[1]*r[6] - x[2]*r[5] + x[3]*r[4];
    t[42] = x[4]*r[3] - x[5]*r[2] + x[6]*r[1];
    t[43] = x[7]*r[0];
#pragma unroll
    for (int i = 0; i < 44; ++i) {
        bf h, l; bsplit(t[i], h, l);
        Th[plane * i + idx] = h; Tl[plane * i + idx] = l;
    }
}

// channel-wise GP (with r normalization folded) + combine (/sqrt2) + MVSiLU
__global__ void k_cw_split(const float* __restrict__ hp, const float* __restrict__ rraw,
                           float* linp, const float* __restrict__ wg,
                           const float* __restrict__ nga,
                           const float* __restrict__ aa, const float* __restrict__ ab,
                           bf* __restrict__ hi, bf* __restrict__ lo) {
    const int M = 512;
    int idx = blockIdx.x * blockDim.x + threadIdx.x;
    size_t plane = (size_t)BQ * M;
    if (idx >= (int)plane) return;
    int n = idx % M;
    float x[8], r[8];
#pragma unroll
    for (int i = 0; i < 8; ++i) { x[i] = hp[plane * i + idx]; r[i] = rraw[plane * i + idx]; }
    {
        float q[4];
        q[0] = r[0]*r[0];
        q[1] = r[1]*r[1] + r[2]*r[2] + r[3]*r[3];
        q[2] = r[4]*r[4] + r[5]*r[5] + r[6]*r[6];
        q[3] = r[7]*r[7];
        float inv[4];
#pragma unroll
        for (int g = 0; g < 4; ++g) {
            float sa = sigmoidf_(nga[n * 4 + g]);
            inv[g] = 1.0f / (sa * (sqrtf(q[g]) - 1.0f) + 1.0f + EPSN);
        }
        const int gm[8] = {0,1,1,1,2,2,2,3};
#pragma unroll
        for (int i = 0; i < 8; ++i) r[i] *= inv[gm[i]];
    }
    float x0=x[0],x1=x[1],x2=x[2],x3=x[3],x4=x[4],x5=x[5],x6=x[6],x7=x[7];
    float r0=r[0],r1=r[1],r2=r[2],r3=r[3],r4=r[4],r5=r[5],r6=r[6],r7=r[7];
    const float* w = wg + n * 20;
    float o0 = w[0]*(x0*r0) + w[4]*(x1*r1 + x2*r2 + x3*r3)
             - w[10]*(x4*r4 + x5*r5 + x6*r6) - w[16]*(x7*r7);
    float o1 = w[1]*x0*r1 + w[5]*x1*r0 + w[6]*(-x2*r4 - x3*r5)
             + w[11]*( x4*r2 + x5*r3) + w[12]*(-x6*r7) + w[17]*(-x7*r6);
    float o2 = w[1]*x0*r2 + w[5]*x2*r0 + w[6]*( x1*r4 - x3*r6)
             + w[11]*(-x4*r1 + x6*r3) + w[12]*( x5*r7) + w[17]*( x7*r5);
    float o3 = w[1]*x0*r3 + w[5]*x3*r0 + w[6]*( x1*r5 + x2*r6)
             + w[11]*(-x5*r1 - x6*r2) + w[12]*(-x4*r7) + w[17]*(-x7*r4);
    float o4 = w[2]*x0*r4 + w[7]*(x1*r2 - x2*r1) + w[8]*( x3*r7)
             + w[13]*x4*r0 + w[14]*(x6*r5 - x5*r6) + w[18]*( x7*r3);
    float o5 = w[2]*x0*r5 + w[7]*(x1*r3 - x3*r1) + w[8]*(-x2*r7)
             + w[13]*x5*r0 + w[14]*(x4*r6 - x6*r4) + w[18]*(-x7*r2);
    float o6 = w[2]*x0*r6 + w[7]*(x2*r3 - x3*r2) + w[8]*( x1*r7)
             + w[13]*x6*r0 + w[14]*(x5*r4 - x4*r5) + w[18]*( x7*r1);
    float o7 = w[3]*x0*r7 + w[9]*(x1*r6 - x2*r5 + x3*r4)
             + w[15]*(x4*r3 - x5*r2 + x6*r1) + w[19]*x7*r0;
    float t[8];
    float oarr[8] = {o0,o1,o2,o3,o4,o5,o6,o7};
#pragma unroll
    for (int i = 0; i < 8; ++i) t[i] = (linp[plane * i + idx] + oarr[i]) * RSQRT2F;
    float inv[4];
    inv[0] = t[0];
    inv[1] = t[1]*t[1] + t[2]*t[2] + t[3]*t[3];
    inv[2] = t[4]*t[4] + t[5]*t[5] + t[6]*t[6];
    inv[3] = t[7]*t[7];
    float s[4];
#pragma unroll
    for (int g = 0; g < 4; ++g)
        s[g] = sigmoidf_(aa[n * 4 + g] * inv[g] + ab[n * 4 + g]);
    const int gm[8] = {0,1,1,1,2,2,2,3};
#pragma unroll
    for (int i = 0; i < 8; ++i) {
        float o = t[i] * s[gm[i]];
        linp[plane * i + idx] = o;
        bf h, l; bsplit(o, h, l);
        hi[plane * i + idx] = h; lo[plane * i + idx] = l;
    }
}

// ===================== host =====================
static void* symaddr(const void* s) { void* p = nullptr; cudaGetSymbolAddress(&p, s); return p; }

extern "C" void kernel_launch(void* const* d_in, const int* in_sizes, int n_in,
                              void* d_out, int out_size) {
    (void)in_sizes; (void)n_in; (void)out_size;
    const float* x     = (const float*)d_in[0];
    const float* lr1_w = (const float*)d_in[1];
    const float* n1_a  = (const float*)d_in[2];
    const float* ll1_w = (const float*)d_in[3];
    const float* ll1_b = (const float*)d_in[4];
    const float* w1    = (const float*)d_in[5];
    const float* act_a = (const float*)d_in[6];
    const float* act_b = (const float*)d_in[7];
    const float* lrg_w = (const float*)d_in[8];
    const float* ng_a  = (const float*)d_in[9];
    const float* llg_w = (const float*)d_in[10];
    const float* llg_b = (const float*)d_in[11];
    const float* wg    = (const float*)d_in[12];
    const float* lr2_w = (const float*)d_in[13];
    const float* n2_a  = (const float*)d_in[14];
    const float* ll2_w = (const float*)d_in[15];
    const float* ll2_b = (const float*)d_in[16];
    const float* w2    = (const float*)d_in[17];
    float* out = (float*)d_out;

    cudaFuncSetAttribute(gemm_bat8_t,  cudaFuncAttributeMaxDynamicSharedMemorySize, SMEM128_3);
    cudaFuncSetAttribute(gemm_bat16_t, cudaFuncAttributeMaxDynamicSharedMemorySize, SMEM128_3);
    cudaFuncSetAttribute(gemm_fused_t<128, false, 3>, cudaFuncAttributeMaxDynamicSharedMemorySize, SMEM128_3);
    cudaFuncSetAttribute(gemm_fused_t<64, true, 2>,   cudaFuncAttributeMaxDynamicSharedMemorySize, SMEM64_2);

    float* xp   = (float*)symaddr(g_xp);
    float* xr   = (float*)symaddr(g_xr);
    float* h    = (float*)symaddr(g_h);
    float* lin  = (float*)symaddr(g_lin);
    bf* xph = (bf*)symaddr(g_xph); bf* xpl = (bf*)symaddr(g_xpl);
    bf* hh  = (bf*)symaddr(g_hh);  bf* hl  = (bf*)symaddr(g_hl);
    bf* lih = (bf*)symaddr(g_lih); bf* lil = (bf*)symaddr(g_lil);
    bf* Th  = (bf*)symaddr(g_Th);  bf* Tl  = (bf*)symaddr(g_Tl);
    bf* lr1h = (bf*)symaddr(g_lr1h); bf* lr1l = (bf*)symaddr(g_lr1l);
    bf* ll1h = (bf*)symaddr(g_ll1h); bf* ll1l = (bf*)symaddr(g_ll1l);
    bf* w1h  = (bf*)symaddr(g_w1h);  bf* w1l  = (bf*)symaddr(g_w1l);
    bf* lrgh = (bf*)symaddr(g_lrgh); bf* lrgl = (bf*)symaddr(g_lrgl);
    bf* llgh = (bf*)symaddr(g_llgh); bf* llgl = (bf*)symaddr(g_llgl);
    bf* lr2h = (bf*)symaddr(g_lr2h); bf* lr2l = (bf*)symaddr(g_lr2l);
    bf* ll2h = (bf*)symaddr(g_ll2h); bf* ll2l = (bf*)symaddr(g_ll2l);
    bf* w2h  = (bf*)symaddr(g_w2h);  bf* w2l  = (bf*)symaddr(g_w2l);

    const int TPB = 256;
    auto nb = [](int total) { return (total + 255) / 256; };

    // single-launch planarize of all weights
    {
        PlanArgs pa;
        pa.j[0] = {lr1_w, lr1h, lr1l, 256*256, 4};
        pa.j[1] = {ll1_w, ll1h, ll1l, 512*256, 4};
        pa.j[2] = {w1,    w1h,  w1l,  512*256, 20};
        pa.j[3] = {lrg_w, lrgh, lrgl, 512*512, 4};
        pa.j[4] = {llg_w, llgh, llgl, 512*512, 4};
        pa.j[5] = {lr2_w, lr2h, lr2l, 512*512, 4};
        pa.j[6] = {ll2_w, ll2h, ll2l, 128*512, 4};
        pa.j[7] = {w2,    w2h,  w2l,  128*512, 20};
        k_planarize_all<<<dim3(1024, 8), TPB>>>(pa);
    }

    // planarize x (fp32 + hi/lo)
    k_transpose_bf<<<nb(BQ*256), TPB>>>(x, xp, xph, xpl, 256);

    static const int j0g[4]   = {0, 1, 4, 7};
    static const int sg[4]    = {1, 3, 3, 1};
    static const int tbase[4] = {0, 4, 22, 40};
    static const int ntri[4]  = {4, 6, 6, 4};
    static const int tri0[6] = {0, 4, 10, 16, 0, 0};
    static const int tri1[6] = {1, 5, 6, 11, 12, 17};
    static const int tri2[6] = {2, 7, 8, 13, 14, 18};
    static const int tri3[6] = {3, 9, 15, 19, 0, 0};
    const int* tris[4] = {tri0, tri1, tri2, tri3};

    // ===== stage 1: xr_raw = mv_linear(x, lr1_w); norm folded into pairfeat =====
    {
        Bat8T a;
        a.Ah = xph; a.Al = xpl; a.Wh = lr1h; a.Wl = lr1l;
        a.C = xr; a.bias = nullptr; a.K = 256; a.N = 256; a.scale = 1.0f;
        gemm_bat8_t<<<dim3(2, 8, 8), 256, SMEM128_3>>>(a);
    }
    k_pairfeat_norm<<<nb(BQ*256), TPB>>>(xp, xr, n1_a, Th, Tl, 256);

    // fused layer 1: h = (mv_linear(x,ll1)+b + fcgp(x,xr,w1)) / sqrt2
    {
        FusedT f; f.K = 256; f.N = 512; f.scale = RSQRT2F;
        size_t plane = (size_t)BQ * 256;
        for (int g = 0; g < 4; ++g) {
            GradeT& gg = f.g[g];
            gg.nseg = 1 + ntri[g];
            gg.C = h + (size_t)j0g[g] * BQ * 512;
            gg.bias = (g == 0) ? ll1_b : nullptr;
            gg.jbase = j0g[g];
            gg.segs[0].Ah = xph + (size_t)j0g[g] * plane;
            gg.segs[0].Al = xpl + (size_t)j0g[g] * plane;
            gg.segs[0].Wh = ll1h + (size_t)g * 512 * 256;
            gg.segs[0].Wl = ll1l + (size_t)g * 512 * 256;
            for (int c = 0; c < ntri[g]; ++c) {
                size_t to = (size_t)(tbase[g] + c * sg[g]) * plane;
                size_t wo = (size_t)tris[g][c] * 512 * 256;
                gg.segs[c + 1].Ah = Th + to; gg.segs[c + 1].Al = Tl + to;
                gg.segs[c + 1].Wh = w1h + wo; gg.segs[c + 1].Wl = w1l + wo;
            }
            for (int c = ntri[g] + 1; c < 7; ++c) gg.segs[c] = gg.segs[0];
        }
        gemm_fused_t<128, false, 3><<<dim3(4, 64), 256, SMEM128_3>>>(f);
    }
    k_mvsilu_split<<<nb(BQ*512), TPB>>>(h, act_a, act_b, hh, hl, 512);

    // ===== stage 2: lrg + llg merged; cw_split normalizes lrg output inline =====
    {
        Bat16T a;
        a.Ah = hh; a.Al = hl;
        a.W1h = lrgh; a.W1l = lrgl; a.W2h = llgh; a.W2l = llgl;
        a.C1 = xr; a.C2 = lin; a.bias2 = llg_b;
        a.K = 512; a.N = 512;
        gemm_bat16_t<<<dim3(4, 8, 16), 256, SMEM128_3>>>(a);
    }
    k_cw_split<<<nb(BQ*512), TPB>>>(h, xr, lin, wg, ng_a, act_a, act_b, lih, lil);
    // h_new lives in `lin` (fp32) and lih/lil (bf16)

    // ===== stage 3: fcgp2 -> out (interleaved epilogue) =====
    {
        Bat8T a;
        a.Ah = lih; a.Al = lil; a.Wh = lr2h; a.Wl = lr2l;
        a.C = xr; a.bias = nullptr; a.K = 512; a.N = 512; a.scale = 1.0f;
        gemm_bat8_t<<<dim3(4, 8, 8), 256, SMEM128_3>>>(a);
    }
    k_pairfeat_norm<<<nb(BQ*512), TPB>>>(lin, xr, n2_a, Th, Tl, 512);
    {
        FusedT f; f.K = 512; f.N = 128; f.scale = RSQRT2F;
        size_t plane = (size_t)BQ * 512;
        for (int g = 0; g < 4; ++g) {
            GradeT& gg = f.g[g];
            gg.nseg = 1 + ntri[g];
            gg.C = out;                      // interleaved direct write
            gg.bias = (g == 0) ? ll2_b : nullptr;
            gg.jbase = j0g[g];
            gg.segs[0].Ah = lih + (size_t)j0g[g] * plane;
            gg.segs[0].Al = lil + (size_t)j0g[g] * plane;
            gg.segs[0].Wh = ll2h + (size_t)g * 128 * 512;
            gg.segs[0].Wl = ll2l + (size_t)g * 128 * 512;
            for (int c = 0; c < ntri[g]; ++c) {
                size_t to = (size_t)(tbase[g] + c * sg[g]) * plane;
                size_t wo = (size_t)tris[g][c] * 128 * 512;
                gg.segs[c + 1].Ah = Th + to; gg.segs[c + 1].Al = Tl + to;
                gg.segs[c + 1].Wh = w2h + wo; gg.segs[c + 1].Wl = w2l + wo;
            }
            for (int c = ntri[g] + 1; c < 7; ++c) gg.segs[c] = gg.segs[0];
        }
        gemm_fused_t<64, true, 2><<<dim3(1, 128), 256, SMEM64_2>>>(f);
    }
}